// round 14
// baseline (speedup 1.0000x reference)
#include <cuda_runtime.h>
#include <cstdint>
#include <cmath>

// FIRE bias: out[1,H,S,S], H=12, S=2048, W=32. Single fused kernel.
// nd(i,j) = LR(|i-j|)*invLN(i); bias[h] piecewise-linear in nd (<=32 ReLU knees).
// Each block (one row i) redundantly builds the 33x12 {slope,icept} table from the
// tiny weights (440 floats), folding invLN(i) into the slopes. Region via binary
// search for the first of 4 consecutive d's + monotone walk. Writes are the
// roofline (~5.4 TB/s pure-write ceiling measured); prologue overlaps across blocks.

#define SDIM 2048
#define HDIM 12
#define WDIM 32
#define NREG 33

__global__ __launch_bounds__(512, 3)
void fire_fused(const float* __restrict__ w1, const float* __restrict__ b1,
                const float* __restrict__ w2, const float* __restrict__ b2,
                const float* __restrict__ cp, const float* __restrict__ Lm,
                const float* __restrict__ iL, float* __restrict__ out) {
    __shared__ float  sW1[WDIM], sB1[WDIM], sB2[HDIM], sW2[HDIM * WDIM];
    __shared__ float  sT[WDIM], sSorted[WDIM];
    __shared__ int    sRank[WDIM];
    __shared__ float  sScal[2];            // {c, thr}
    __shared__ float2 shTab[NREG * HDIM];  // slope premultiplied by invLN(i)
    __shared__ float  sLRT[64];            // t_k * LN(i), +inf padded

    const int tid = threadIdx.x;
    const int i   = blockIdx.x;

    // ---- prologue: load weights ----
    if (tid < WDIM)                 { sW1[tid] = w1[tid]; sB1[tid] = b1[tid]; }
    else if (tid < WDIM + HDIM * WDIM) sW2[tid - WDIM] = w2[tid - WDIM];
    else if (tid < WDIM + HDIM * WDIM + HDIM) sB2[tid - WDIM - HDIM * WDIM] = b2[tid - WDIM - HDIM * WDIM];
    else if (tid == 500) sScal[0] = *cp;
    else if (tid == 501) sScal[1] = fabsf((*Lm) * (*iL));
    __syncthreads();

    // ---- thresholds ----
    if (tid < WDIM) {
        const float w1v = sW1[tid];
        sT[tid] = (w1v != 0.0f) ? (-sB1[tid] / w1v) : 0.0f;
    }
    __syncthreads();
    if (tid < WDIM) {
        const float t = sT[tid];
        int r = 0;
        for (int k = 0; k < WDIM; k++) {
            const float tk = sT[k];
            if (tk < t || (tk == t && k < tid)) r++;
        }
        sRank[tid] = r;
        sSorted[r] = t;
    }
    __syncthreads();

    // row-uniform log-norm (MUFU; every thread computes, all identical)
    const float c     = sScal[0];
    const float thr   = sScal[1];
    const float pn    = fmaxf((float)i, thr) + 1e-6f;
    const float ln    = __logf(fabsf(c * pn) + 1.000001f);
    const float invln = __fdividef(1.0f, ln);

    // ---- per-block table build (invln folded into slope) ----
    if (tid < NREG * HDIM) {
        const int r = tid / HDIM;
        const int h = tid % HDIM;
        float sl = 0.0f, ic = 0.0f;
        for (int w = 0; w < WDIM; w++) {
            const float w1v = sW1[w], b1v = sB1[w];
            bool act;
            if (w1v > 0.0f)      act = (sRank[w] < r);
            else if (w1v < 0.0f) act = (sRank[w] >= r);
            else                 act = (b1v > 0.0f);
            if (act) {
                const float w2v = sW2[h * WDIM + w];
                sl += w1v * w2v;
                ic += b1v * w2v;
            }
        }
        shTab[tid] = make_float2(sl * invln, ic + sB2[h]);
    }
    if (tid >= 448 && tid < 448 + 64) {
        const int k = tid - 448;
        sLRT[k] = (k < WDIM) ? sSorted[k] * ln : __int_as_float(0x7f800000);
    }
    __syncthreads();

    // ---- main body: 4 consecutive columns per thread ----
    const int j0 = tid * 4;
    const float K = fmaf(1e-6f, c, 1.000001f);  // (d+eps)*c + 1 + eps = d*c + K
    const float lr0 = __logf(fmaf((float)abs(i - j0),       c, K));
    const float lr1 = __logf(fmaf((float)abs(i - (j0 + 1)), c, K));
    const float lr2 = __logf(fmaf((float)abs(i - (j0 + 2)), c, K));
    const float lr3 = __logf(fmaf((float)abs(i - (j0 + 3)), c, K));

    int r0 = 0;
#pragma unroll
    for (int s = 32; s >= 1; s >>= 1)
        r0 += (lr0 >= sLRT[r0 + s - 1]) ? s : 0;
    int r1 = r0;
    while (lr1 >= sLRT[r1]) r1++;
    while (r1 > 0 && lr1 < sLRT[r1 - 1]) r1--;
    int r2 = r1;
    while (lr2 >= sLRT[r2]) r2++;
    while (r2 > 0 && lr2 < sLRT[r2 - 1]) r2--;
    int r3 = r2;
    while (lr3 >= sLRT[r3]) r3++;
    while (r3 > 0 && lr3 < sLRT[r3 - 1]) r3--;

    float* op = out + (size_t)i * SDIM + j0;
    if ((r0 == r1) & (r1 == r2) & (r2 == r3)) {
        const float2* row = shTab + r0 * HDIM;
#pragma unroll
        for (int h = 0; h < HDIM; h++) {
            const float2 sb = row[h];
            float4 v = make_float4(fmaf(sb.x, lr0, sb.y), fmaf(sb.x, lr1, sb.y),
                                   fmaf(sb.x, lr2, sb.y), fmaf(sb.x, lr3, sb.y));
            __stcs(reinterpret_cast<float4*>(op + (size_t)h * SDIM * SDIM), v);
        }
    } else {
#pragma unroll
        for (int h = 0; h < HDIM; h++) {
            const float2 a = shTab[r0 * HDIM + h];
            const float2 b = shTab[r1 * HDIM + h];
            const float2 cc = shTab[r2 * HDIM + h];
            const float2 d = shTab[r3 * HDIM + h];
            float4 v = make_float4(fmaf(a.x, lr0, a.y), fmaf(b.x, lr1, b.y),
                                   fmaf(cc.x, lr2, cc.y), fmaf(d.x, lr3, d.y));
            __stcs(reinterpret_cast<float4*>(op + (size_t)h * SDIM * SDIM), v);
        }
    }
}

extern "C" void kernel_launch(void* const* d_in, const int* in_sizes, int n_in,
                              void* d_out, int out_size) {
    // inputs: x(unused), w1[32], b1[32], w2[12*32], b2[12], c, L_multiplier, init_L
    const float* w1 = (const float*)d_in[1];
    const float* b1 = (const float*)d_in[2];
    const float* w2 = (const float*)d_in[3];
    const float* b2 = (const float*)d_in[4];
    const float* c  = (const float*)d_in[5];
    const float* Lm = (const float*)d_in[6];
    const float* iL = (const float*)d_in[7];
    (void)in_sizes; (void)n_in; (void)out_size;

    fire_fused<<<SDIM, 512>>>(w1, b1, w2, b2, c, Lm, iL, (float*)d_out);
}